// round 15
// baseline (speedup 1.0000x reference)
#include <cuda_runtime.h>
#include <cuda_fp16.h>
#include <math.h>
#include <stdint.h>

#define NROWS 32768
#define DIM 1024
#define NRES 21

// ---------------- scratch (no cudaMalloc allowed) ----------------
__device__ float g_act[(size_t)NROWS * DIM];
__device__ float g_ang[(size_t)NROWS * 14];
__device__ float g_wangT[14 * DIM];                 // transposed w_ang [14][1024]
__device__ __half g_wt[3][(size_t)DIM * DIM];       // transposed fp16 weights [n][k]
__device__ __half g_sa_hi[(size_t)NROWS * DIM];     // activation hi ping
__device__ __half g_sb_hi[(size_t)NROWS * DIM];     // activation hi pong

// ---------------- PTX helpers (baseline compute_103 safe) ----------------
__device__ __forceinline__ uint32_t smem_to_u32(const void* p) {
    uint32_t a;
    asm("{ .reg .u64 t; cvta.to.shared.u64 t, %1; cvt.u32.u64 %0, t; }" : "=r"(a) : "l"(p));
    return a;
}
__device__ __forceinline__ void ldsm4(uint32_t (&r)[4], uint32_t addr) {
    asm volatile("ldmatrix.sync.aligned.m8n8.x4.shared.b16 {%0,%1,%2,%3}, [%4];"
                 : "=r"(r[0]), "=r"(r[1]), "=r"(r[2]), "=r"(r[3]) : "r"(addr));
}
__device__ __forceinline__ void mma_f16(float* d, const uint32_t* a, const uint32_t* b) {
    asm("mma.sync.aligned.m16n8k16.row.col.f32.f16.f16.f32 "
        "{%0,%1,%2,%3}, {%4,%5,%6,%7}, {%8,%9}, {%0,%1,%2,%3};"
        : "+f"(d[0]), "+f"(d[1]), "+f"(d[2]), "+f"(d[3])
        : "r"(a[0]), "r"(a[1]), "r"(a[2]), "r"(a[3]), "r"(b[0]), "r"(b[1]));
}
__device__ __forceinline__ void cp16(uint32_t dst, const void* src) {
    asm volatile("cp.async.cg.shared.global [%0], [%1], 16;" :: "r"(dst), "l"(src));
}
__device__ __forceinline__ void cp_commit() {
    asm volatile("cp.async.commit_group;" ::: "memory");
}
template<int N>
__device__ __forceinline__ void cp_wait() {
    asm volatile("cp.async.wait_group %0;" :: "n"(N) : "memory");
}
__device__ __forceinline__ uint32_t pack_h2(__half x, __half y) {
    __half2 t; t.x = x; t.y = y;
    return *(uint32_t*)&t;
}

// ---------------- GEMM (single-plane fp16, 128B rows, K64, A+B prefetch) ----------------
#define KCHUNK 64
#define NITERS (DIM / KCHUNK)     // 16
#define TILE_S 16384
#define STAGE_S (2 * TILE_S)      // 32768
#define NSTAGE 3
#define SMEM_TOTAL (NSTAGE * STAGE_S)   // 98304

// RESID: C += prev C ; WC: write fp32 C ; WSPLIT: write fp16 hi of relu(C)
template<int RESID, int WC, int WSPLIT>
__global__ __launch_bounds__(256, 2) void gemm_mma(
    const __half* __restrict__ Ah, const __half* __restrict__ Bh,
    const float* __restrict__ bias, float bias_scale,
    float* __restrict__ C, __half* __restrict__ Shi)
{
    extern __shared__ char smem[];
    const uint32_t sb = smem_to_u32(smem);
    const int tid = threadIdx.x;
    const int wid = tid >> 5;
    const int lane = tid & 31;
    const int bx = blockIdx.x, by = blockIdx.y;
    const int wm = wid & 3;
    const int wn = wid >> 2;

    float d[2][8][4];
    #pragma unroll
    for (int i = 0; i < 2; i++)
        #pragma unroll
        for (int j = 0; j < 8; j++)
            #pragma unroll
            for (int q = 0; q < 4; q++) d[i][j][q] = 0.f;

    auto issue = [&](int kc) {
        const int s = kc % NSTAGE;
        const uint32_t stage = sb + s * STAGE_S;
        #pragma unroll
        for (int t = 0; t < 8; t++) {
            const int i = tid + t * 256;
            const int tile = i >> 10;          // 0 = A, 1 = B
            const int idx = i & 1023;
            const int row = idx >> 3;
            const int unit = idx & 7;
            const __half* plane = tile ? Bh : Ah;
            const int grow = (tile ? bx : by) * 128 + row;
            const char* src = (const char*)plane + (size_t)grow * (DIM * 2)
                              + kc * 128 + unit * 16;
            const uint32_t dst = stage + tile * TILE_S + row * 128
                                 + ((unit ^ (row & 7)) << 4);
            cp16(dst, src);
        }
        cp_commit();
    };

    issue(0);
    issue(1);

    const int arow0 = wm * 32 + (lane & 15);
    const int brlane = (lane & 7) + (((lane >> 4) & 1) << 3);

    for (int kc = 0; kc < NITERS; kc++) {
        cp_wait<1>();
        __syncthreads();
        if (kc + 2 < NITERS) issue(kc + 2);

        const uint32_t stage = sb + (kc % NSTAGE) * STAGE_S;
        auto aaddr = [&](int kh, int mt) {
            const int arow = arow0 + mt * 16;
            const int aunit = kh * 2 + (lane >> 4);
            return stage + arow * 128 + ((aunit ^ (arow & 7)) << 4);
        };
        // A double-buffered across kh
        uint32_t ahb[2][2][4];
        ldsm4(ahb[0][0], aaddr(0, 0));
        ldsm4(ahb[0][1], aaddr(0, 1));
        #pragma unroll
        for (int kh = 0; kh < 4; kh++) {
            const int acur = kh & 1;
            const int bunit = kh * 2 + ((lane >> 3) & 1);
            auto baddr = [&](int ntp) {
                const int brow = wn * 64 + ntp * 16 + brlane;
                return stage + TILE_S + brow * 128 + ((bunit ^ (brow & 7)) << 4);
            };
            uint32_t bh[2][4];
            ldsm4(bh[0], baddr(0));
            if (kh < 3) {                       // prefetch next kh's A fragments
                ldsm4(ahb[acur ^ 1][0], aaddr(kh + 1, 0));
                ldsm4(ahb[acur ^ 1][1], aaddr(kh + 1, 1));
            }
            #pragma unroll
            for (int ntp = 0; ntp < 4; ntp++) {
                const int cur = ntp & 1;
                if (ntp < 3) ldsm4(bh[cur ^ 1], baddr(ntp + 1));
                #pragma unroll
                for (int mt = 0; mt < 2; mt++) {
                    #pragma unroll
                    for (int c = 0; c < 2; c++)
                        mma_f16(d[mt][ntp * 2 + c], ahb[acur][mt], &bh[cur][2 * c]);
                }
            }
        }
    }

    // ---- epilogue ----
    const int rq = lane >> 2;
    const int cq = (lane & 3) * 2;
    #pragma unroll
    for (int mt = 0; mt < 2; mt++) {
        #pragma unroll
        for (int nt = 0; nt < 8; nt++) {
            const int col = bx * 128 + wn * 64 + nt * 8 + cq;
            const float b0 = bias_scale * bias[col];
            const float b1 = bias_scale * bias[col + 1];
            #pragma unroll
            for (int hrow = 0; hrow < 2; hrow++) {
                const int row = by * 128 + wm * 32 + mt * 16 + rq + hrow * 8;
                float vx = d[mt][nt][hrow * 2 + 0] + b0;
                float vy = d[mt][nt][hrow * 2 + 1] + b1;
                float* cp = C + (size_t)row * DIM + col;
                if (RESID) {
                    float2 old = *(const float2*)cp;
                    vx += old.x; vy += old.y;
                }
                if (WC) *(float2*)cp = make_float2(vx, vy);
                if (WSPLIT) {
                    const size_t o = (size_t)row * DIM + col;
                    *(uint32_t*)(Shi + o) = pack_h2(__float2half(fmaxf(vx, 0.f)),
                                                    __float2half(fmaxf(vy, 0.f)));
                }
            }
        }
    }
}

// ---------------- fuse0: fp16(relu(rep0)+relu(rep1)) ----------------
__global__ __launch_bounds__(256) void fuse0(
    const float* __restrict__ rep0, const float* __restrict__ rep1,
    __half* __restrict__ Shi)
{
    const size_t i = ((size_t)blockIdx.x * blockDim.x + threadIdx.x) * 4;
    float4 a = *(const float4*)(rep0 + i);
    float4 b = *(const float4*)(rep1 + i);
    float v0 = fmaxf(a.x, 0.f) + fmaxf(b.x, 0.f);
    float v1 = fmaxf(a.y, 0.f) + fmaxf(b.y, 0.f);
    float v2 = fmaxf(a.z, 0.f) + fmaxf(b.z, 0.f);
    float v3 = fmaxf(a.w, 0.f) + fmaxf(b.w, 0.f);
    uint2 o;
    o.x = pack_h2(__float2half(v0), __float2half(v1));
    o.y = pack_h2(__float2half(v2), __float2half(v3));
    *(uint2*)(Shi + i) = o;
}

// ---------------- merged weight transpose to fp16 (z selects weight) ----------------
__global__ __launch_bounds__(256) void prep_w3(
    const float* __restrict__ W0, const float* __restrict__ W1,
    const float* __restrict__ W2, __half* __restrict__ Wt)
{
    __shared__ float t[32][33];
    const float* W = (blockIdx.z == 0) ? W0 : (blockIdx.z == 1) ? W1 : W2;
    __half* dst = Wt + (size_t)blockIdx.z * DIM * DIM;
    const int n0 = blockIdx.x * 32, k0 = blockIdx.y * 32;
    const int tx = threadIdx.x, ty = threadIdx.y;  // (32, 8)
    #pragma unroll
    for (int i = 0; i < 4; i++)
        t[ty + i * 8][tx] = W[(size_t)(k0 + ty + i * 8) * DIM + n0 + tx];
    __syncthreads();
    #pragma unroll
    for (int i = 0; i < 4; i++)
        dst[(size_t)(n0 + ty + i * 8) * DIM + k0 + tx] = __float2half(t[tx][ty + i * 8]);
}

// ---------------- w_ang transpose (exact fp32 copy) ----------------
__global__ __launch_bounds__(256) void prep_wang(const float* __restrict__ W,
                                                 float* __restrict__ WT)
{
    const int idx = blockIdx.x * 256 + threadIdx.x;   // 14*1024 total
    if (idx >= 14 * DIM) return;
    const int j = idx / DIM;
    const int i = idx % DIM;
    WT[j * DIM + i] = W[i * 14 + j];
}

// ---------------- torsion head: coalesced, float4 loads ----------------
__global__ __launch_bounds__(256) void ang_kernel(
    const float* __restrict__ act, const float* __restrict__ wT,
    const float* __restrict__ b_ang, float* __restrict__ angbuf)
{
    const int gw = (int)((blockIdx.x * blockDim.x + threadIdx.x) >> 5);
    const int lane = threadIdx.x & 31;
    if (gw >= NROWS) return;
    const float4* row = (const float4*)(act + (size_t)gw * DIM);
    float acc[14] = {};
    #pragma unroll
    for (int it = 0; it < 8; it++) {
        const int i4 = lane + it * 32;
        float4 a4 = row[i4];
        float a[4] = {fmaxf(a4.x, 0.f), fmaxf(a4.y, 0.f),
                      fmaxf(a4.z, 0.f), fmaxf(a4.w, 0.f)};
        #pragma unroll
        for (int j = 0; j < 14; j++) {
            const float4 w4 = *(const float4*)(wT + j * DIM + i4 * 4);
            acc[j] = fmaf(a[0], w4.x, acc[j]);
            acc[j] = fmaf(a[1], w4.y, acc[j]);
            acc[j] = fmaf(a[2], w4.z, acc[j]);
            acc[j] = fmaf(a[3], w4.w, acc[j]);
        }
    }
    #pragma unroll
    for (int j = 0; j < 14; j++) {
        #pragma unroll
        for (int off = 16; off; off >>= 1)
            acc[j] += __shfl_down_sync(0xffffffffu, acc[j], off);
    }
    if (lane == 0) {
        float* o = angbuf + (size_t)gw * 14;
        #pragma unroll
        for (int j = 0; j < 14; j++) o[j] = acc[j] + b_ang[j];
    }
}

// ---------------- per-residue geometry ----------------
__global__ __launch_bounds__(128) void epilogue_kernel(
    const float* __restrict__ angbuf,
    const float* __restrict__ rigids, const float* __restrict__ def_frames,
    const float* __restrict__ lit_pos, const float* __restrict__ atom_mask,
    const int* __restrict__ aatype, const int* __restrict__ gidx,
    float* __restrict__ out_angles, float* __restrict__ out_pred,
    float* __restrict__ out_frames)
{
    const int n = blockIdx.x * blockDim.x + threadIdx.x;
    if (n >= NROWS) return;
    const int aa = aatype[n];

    float s[8], c[8];
    s[0] = 0.f; c[0] = 1.f;
    #pragma unroll
    for (int i = 0; i < 7; i++) {
        float ss = angbuf[(size_t)n * 14 + 2 * i];
        float cc = angbuf[(size_t)n * 14 + 2 * i + 1];
        float inv = rsqrtf(fmaxf(ss * ss + cc * cc, 1e-12f));
        ss *= inv; cc *= inv;
        s[i + 1] = ss; c[i + 1] = cc;
        out_angles[(size_t)n * 14 + 2 * i] = ss;
        out_angles[(size_t)n * 14 + 2 * i + 1] = cc;
    }

    float FR[8][9], FT[8][3];
    #pragma unroll
    for (int k = 0; k < 8; k++) {
        const float* D = def_frames + ((size_t)aa * 8 + k) * 16;
        #pragma unroll
        for (int r = 0; r < 3; r++) {
            float d1 = D[r * 4 + 1], d2 = D[r * 4 + 2];
            FR[k][r * 3 + 0] = D[r * 4 + 0];
            FR[k][r * 3 + 1] = c[k] * d1 + s[k] * d2;
            FR[k][r * 3 + 2] = -s[k] * d1 + c[k] * d2;
            FT[k][r] = D[r * 4 + 3];
        }
    }

    #pragma unroll
    for (int k = 5; k <= 7; k++) {
        float R[9], T[3];
        #pragma unroll
        for (int r = 0; r < 3; r++) {
            #pragma unroll
            for (int cc2 = 0; cc2 < 3; cc2++)
                R[r * 3 + cc2] = FR[k - 1][r * 3 + 0] * FR[k][0 + cc2]
                               + FR[k - 1][r * 3 + 1] * FR[k][3 + cc2]
                               + FR[k - 1][r * 3 + 2] * FR[k][6 + cc2];
            T[r] = FR[k - 1][r * 3 + 0] * FT[k][0]
                 + FR[k - 1][r * 3 + 1] * FT[k][1]
                 + FR[k - 1][r * 3 + 2] * FT[k][2] + FT[k - 1][r];
        }
        #pragma unroll
        for (int q = 0; q < 9; q++) FR[k][q] = R[q];
        FT[k][0] = T[0]; FT[k][1] = T[1]; FT[k][2] = T[2];
    }

    const float* rg = rigids + (size_t)n * 16;
    float R0[9] = {rg[0], rg[1], rg[2], rg[4], rg[5], rg[6], rg[8], rg[9], rg[10]};
    float t0[3] = {rg[3], rg[7], rg[11]};

    #pragma unroll
    for (int k = 0; k < 8; k++) {
        float R[9], T[3];
        #pragma unroll
        for (int r = 0; r < 3; r++) {
            #pragma unroll
            for (int cc2 = 0; cc2 < 3; cc2++)
                R[r * 3 + cc2] = R0[r * 3 + 0] * FR[k][0 + cc2]
                               + R0[r * 3 + 1] * FR[k][3 + cc2]
                               + R0[r * 3 + 2] * FR[k][6 + cc2];
            T[r] = R0[r * 3 + 0] * FT[k][0] + R0[r * 3 + 1] * FT[k][1]
                 + R0[r * 3 + 2] * FT[k][2] + t0[r];
        }
        #pragma unroll
        for (int q = 0; q < 9; q++) FR[k][q] = R[q];
        FT[k][0] = T[0]; FT[k][1] = T[1]; FT[k][2] = T[2];

        float* of = out_frames + ((size_t)n * 8 + k) * 16;
        *(float4*)(of + 0)  = make_float4(R[0], R[1], R[2], T[0]);
        *(float4*)(of + 4)  = make_float4(R[3], R[4], R[5], T[1]);
        *(float4*)(of + 8)  = make_float4(R[6], R[7], R[8], T[2]);
        *(float4*)(of + 12) = make_float4(0.f, 0.f, 0.f, 1.f);
    }

    #pragma unroll
    for (int a = 0; a < 14; a++) {
        int g = gidx[aa * 14 + a];
        const float* p = lit_pos + ((size_t)aa * 14 + a) * 3;
        float m = atom_mask[aa * 14 + a];
        float px = p[0], py = p[1], pz = p[2];
        float* op = out_pred + ((size_t)n * 14 + a) * 3;
        op[0] = (FR[g][0] * px + FR[g][1] * py + FR[g][2] * pz + FT[g][0]) * m;
        op[1] = (FR[g][3] * px + FR[g][4] * py + FR[g][5] * pz + FT[g][1]) * m;
        op[2] = (FR[g][6] * px + FR[g][7] * py + FR[g][8] * pz + FT[g][2]) * m;
    }
}

// ---------------- launch ----------------
extern "C" void kernel_launch(void* const* d_in, const int* in_sizes, int n_in,
                              void* d_out, int out_size)
{
    const float* rep0       = (const float*)d_in[0];
    const float* rep1       = (const float*)d_in[1];
    const float* w_in       = (const float*)d_in[2];
    const float* b_in       = (const float*)d_in[3];
    const float* w1         = (const float*)d_in[4];
    const float* b1         = (const float*)d_in[5];
    const float* w2         = (const float*)d_in[6];
    const float* b2         = (const float*)d_in[7];
    const float* w_ang      = (const float*)d_in[8];
    const float* b_ang      = (const float*)d_in[9];
    const float* rigids     = (const float*)d_in[10];
    const float* def_frames = (const float*)d_in[11];
    const float* lit_pos    = (const float*)d_in[12];
    const float* atom_mask  = (const float*)d_in[13];
    const int*   aatype     = (const int*)d_in[14];
    const int*   gidx       = (const int*)d_in[15];

    float *act, *angb, *wangT;
    __half *wt, *sah, *sbh;
    cudaGetSymbolAddress((void**)&act, g_act);
    cudaGetSymbolAddress((void**)&angb, g_ang);
    cudaGetSymbolAddress((void**)&wangT, g_wangT);
    cudaGetSymbolAddress((void**)&wt, g_wt);
    cudaGetSymbolAddress((void**)&sah, g_sa_hi);
    cudaGetSymbolAddress((void**)&sbh, g_sb_hi);
    const size_t WSZ = (size_t)DIM * DIM;

    cudaFuncSetAttribute(gemm_mma<0,1,1>, cudaFuncAttributeMaxDynamicSharedMemorySize, SMEM_TOTAL);
    cudaFuncSetAttribute(gemm_mma<0,0,1>, cudaFuncAttributeMaxDynamicSharedMemorySize, SMEM_TOTAL);
    cudaFuncSetAttribute(gemm_mma<1,1,1>, cudaFuncAttributeMaxDynamicSharedMemorySize, SMEM_TOTAL);
    cudaFuncSetAttribute(gemm_mma<1,1,0>, cudaFuncAttributeMaxDynamicSharedMemorySize, SMEM_TOTAL);

    dim3 pg(DIM / 32, DIM / 32, 3), pb(32, 8);
    prep_w3<<<pg, pb>>>(w_in, w1, w2, wt);
    prep_wang<<<(14 * DIM + 255) / 256, 256>>>(w_ang, wangT);

    fuse0<<<(NROWS * DIM) / (256 * 4), 256>>>(rep0, rep1, sah);

    dim3 grid(DIM / 128, NROWS / 128);  // (8, 256)

    gemm_mma<0,1,1><<<grid, 256, SMEM_TOTAL>>>(sah, wt + 0*WSZ, b_in, 2.f, act, sbh);
    gemm_mma<0,0,1><<<grid, 256, SMEM_TOTAL>>>(sbh, wt + 1*WSZ, b1, 1.f, act, sah);
    gemm_mma<1,1,1><<<grid, 256, SMEM_TOTAL>>>(sah, wt + 2*WSZ, b2, 1.f, act, sbh);
    gemm_mma<0,0,1><<<grid, 256, SMEM_TOTAL>>>(sbh, wt + 1*WSZ, b1, 1.f, act, sah);
    gemm_mma<1,1,0><<<grid, 256, SMEM_TOTAL>>>(sah, wt + 2*WSZ, b2, 1.f, act, sbh);

    ang_kernel<<<NROWS / 8, 256>>>(act, wangT, b_ang, angb);

    float* out = (float*)d_out;
    float* out_angles = out;
    float* out_pred   = out + (size_t)NROWS * 14;
    float* out_frames = out + (size_t)NROWS * 56;
    epilogue_kernel<<<(NROWS + 127) / 128, 128>>>(
        angb, rigids, def_frames, lit_pos, atom_mask, aatype, gidx,
        out_angles, out_pred, out_frames);
}